// round 6
// baseline (speedup 1.0000x reference)
#include <cuda_runtime.h>
#include <cuda_bf16.h>

// Matvec: out[n] = sum_d fc[n][d] * input[d],  n = 50, d = 1048576.
//
// R5 finding: one-wave layout lifted DRAM to 71.6% but it plateaus there —
// steady-state idle, not scheduling. Model: at occ 60% (5 CTAs/SM, regs=44)
// the SM-wide pool of outstanding LDGs is too shallow to keep HBM queues
// full near saturation. Fix: force 6 CTAs/SM (__launch_bounds__(256,6),
// regs target 42) and regrow the one-wave grid to 10 groups x 88 CTAs = 880
// (<= 888 slots). 25% more warps -> 25% deeper load queues.

#define RPC 5                      // rows per CTA group
#define CPG 88                     // CTAs per row-group (10*88=880, one wave @ occ 6)
#define N_ROWS_MAX 64

__device__ float g_partials[N_ROWS_MAX * CPG];
__device__ int   g_arrive[N_ROWS_MAX / RPC + 1];   // zero-initialized

__global__ void __launch_bounds__(256, 6) matvec_pers_kernel(
    const float* __restrict__ inp,
    const float* __restrict__ fc,
    float* __restrict__ out,
    int D)
{
    const int group = blockIdx.y;            // rows [5g, 5g+5)
    const int cta   = blockIdx.x;            // 0..CPG-1 within group
    const int row0  = group * RPC;
    const int vec_total = D / 4;             // 262144 float4 per row
    const int stride    = CPG * 256;         // grid-stride within the group

    const float4* __restrict__ a  = reinterpret_cast<const float4*>(inp);
    const float4* __restrict__ b0 = reinterpret_cast<const float4*>(fc + (size_t)(row0 + 0) * D);
    const float4* __restrict__ b1 = reinterpret_cast<const float4*>(fc + (size_t)(row0 + 1) * D);
    const float4* __restrict__ b2 = reinterpret_cast<const float4*>(fc + (size_t)(row0 + 2) * D);
    const float4* __restrict__ b3 = reinterpret_cast<const float4*>(fc + (size_t)(row0 + 3) * D);
    const float4* __restrict__ b4 = reinterpret_cast<const float4*>(fc + (size_t)(row0 + 4) * D);

    float s0 = 0.f, s1 = 0.f, s2 = 0.f, s3 = 0.f, s4 = 0.f;

    #pragma unroll 2
    for (int i = cta * 256 + threadIdx.x; i < vec_total; i += stride) {
        // 6 independent 16B loads per iteration body.
        float4 av = __ldg(a + i);            // input: L2-resident, reused 10x
        float4 v0 = __ldcs(b0 + i);          // fc: streamed, evict-first
        float4 v1 = __ldcs(b1 + i);
        float4 v2 = __ldcs(b2 + i);
        float4 v3 = __ldcs(b3 + i);
        float4 v4 = __ldcs(b4 + i);

        s0 = fmaf(av.x, v0.x, s0); s0 = fmaf(av.y, v0.y, s0);
        s0 = fmaf(av.z, v0.z, s0); s0 = fmaf(av.w, v0.w, s0);
        s1 = fmaf(av.x, v1.x, s1); s1 = fmaf(av.y, v1.y, s1);
        s1 = fmaf(av.z, v1.z, s1); s1 = fmaf(av.w, v1.w, s1);
        s2 = fmaf(av.x, v2.x, s2); s2 = fmaf(av.y, v2.y, s2);
        s2 = fmaf(av.z, v2.z, s2); s2 = fmaf(av.w, v2.w, s2);
        s3 = fmaf(av.x, v3.x, s3); s3 = fmaf(av.y, v3.y, s3);
        s3 = fmaf(av.z, v3.z, s3); s3 = fmaf(av.w, v3.w, s3);
        s4 = fmaf(av.x, v4.x, s4); s4 = fmaf(av.y, v4.y, s4);
        s4 = fmaf(av.z, v4.z, s4); s4 = fmaf(av.w, v4.w, s4);
    }

    // Block reduction for 5 sums.
    float s[RPC] = {s0, s1, s2, s3, s4};
    __shared__ float warp_sums[8][RPC];
    #pragma unroll
    for (int r = 0; r < RPC; r++) {
        float v = s[r];
        #pragma unroll
        for (int off = 16; off > 0; off >>= 1)
            v += __shfl_down_sync(0xFFFFFFFFu, v, off);
        if ((threadIdx.x & 31) == 0)
            warp_sums[threadIdx.x >> 5][r] = v;
    }
    __syncthreads();

    __shared__ bool is_last;
    if (threadIdx.x < RPC) {
        float v = 0.f;
        #pragma unroll
        for (int w = 0; w < 8; w++) v += warp_sums[w][threadIdx.x];
        g_partials[(row0 + threadIdx.x) * CPG + cta] = v;
    }
    __syncthreads();                 // partials visible before fence+count
    if (threadIdx.x == 0) {
        __threadfence();
        int old = atomicAdd(&g_arrive[group], 1);
        is_last = (old == CPG - 1);
    }
    __syncthreads();

    // Last CTA of the group: deterministic final sum of CPG partials per row.
    // Warp r handles row r: lanes cover partials lid, lid+32, (lid+64 if <CPG).
    if (is_last) {
        __threadfence();             // acquire
        const int w   = threadIdx.x >> 5;
        const int lid = threadIdx.x & 31;
        if (w < RPC) {
            const float* p = &g_partials[(row0 + w) * CPG];
            float v = p[lid] + p[lid + 32];
            if (lid + 64 < CPG) v += p[lid + 64];
            #pragma unroll
            for (int off = 16; off > 0; off >>= 1)
                v += __shfl_down_sync(0xFFFFFFFFu, v, off);
            if (lid == 0)
                out[row0 + w] = v;
        }
        __syncthreads();
        if (threadIdx.x == 0)
            g_arrive[group] = 0;     // reset for next graph replay
    }
}

extern "C" void kernel_launch(void* const* d_in, const int* in_sizes, int n_in,
                              void* d_out, int out_size)
{
    const float* inp = (const float*)d_in[0];   // [D]
    const float* fc  = (const float*)d_in[1];   // [N_ROWS, D]
    float* out       = (float*)d_out;           // [N_ROWS]

    const int D      = in_sizes[0];
    const int groups = out_size / RPC;          // 10 for n_rows=50

    dim3 grid(CPG, groups);
    matvec_pers_kernel<<<grid, 256>>>(inp, fc, out, D);
}